// round 13
// baseline (speedup 1.0000x reference)
#include <cuda_runtime.h>

#define NP 300000
#define NC 10000
#define MAINT 320

// ---- scratch (device globals; zero-initialized at module load) ----
__device__ int g_count[NC];          // re-zeroed by scan_kernel after use
__device__ int g_offsets[NC + 1];
__device__ unsigned g_packed[NP];    // (center<<18)|(species<<16)|rank
__device__ unsigned g_order[NP];     // (pair_index<<2)|species

// ---------------------------------------------------------------------------
// Histogram with fused int64/int32 detection. Odd 32-bit words of int64 index
// data (values < 2^31) are all zero; for int32 species values 0..3 the odds
// of 256 sampled words all being zero are 4^-256. The atomicAdd return value
// is the pair's rank within its center, so the scatter pass needs no atomics.
// ---------------------------------------------------------------------------
__global__ void hist_kernel(const int* __restrict__ dens,
                            const int* __restrict__ sp) {
    __shared__ int s_any;
    if (threadIdx.x == 0) s_any = 0;
    __syncthreads();
    if (threadIdx.x < 256) {
        int v = sp[2 * threadIdx.x + 1];
        if (v) atomicOr(&s_any, 1);
    }
    __syncthreads();
    int st = s_any ? 1 : 2;   // any nonzero odd word -> int32 (stride 1)

    int p = blockIdx.x * blockDim.x + threadIdx.x;
    if (p < NP) {
        int c = dens[p * st];
        int s = sp[p * st] & 3;
        unsigned rank = (unsigned)atomicAdd(&g_count[c], 1);
        g_packed[p] = ((unsigned)c << 18) | ((unsigned)s << 16) | rank;
    }
}

// ---------------------------------------------------------------------------
// Single-block exclusive scan over 10k counts; re-zeros g_count for the next
// graph replay (device globals are only auto-zeroed at module load).
// ---------------------------------------------------------------------------
__global__ __launch_bounds__(1024) void scan_kernel() {
    __shared__ int sc[NC];
    __shared__ int wsum[32];
    int t = threadIdx.x;
    for (int i = t; i < NC; i += 1024) sc[i] = g_count[i];
    __syncthreads();

    const int PER = (NC + 1023) / 1024;  // 10
    int base = t * PER;
    int local[PER];
    int sum = 0;
#pragma unroll
    for (int k = 0; k < PER; k++) {
        int i = base + k;
        int c = (i < NC) ? sc[i] : 0;
        local[k] = c;
        sum += c;
    }
    int lane = t & 31, warp = t >> 5;
    int inc = sum;
#pragma unroll
    for (int off = 1; off < 32; off <<= 1) {
        int n = __shfl_up_sync(0xffffffffu, inc, off);
        if (lane >= off) inc += n;
    }
    if (lane == 31) wsum[warp] = inc;
    __syncthreads();
    if (warp == 0) {
        int v = wsum[lane];
#pragma unroll
        for (int off = 1; off < 32; off <<= 1) {
            int n = __shfl_up_sync(0xffffffffu, v, off);
            if (lane >= off) v += n;
        }
        wsum[lane] = v;
    }
    __syncthreads();
    int run = inc - sum + (warp ? wsum[warp - 1] : 0);
#pragma unroll
    for (int k = 0; k < PER; k++) {
        int i = base + k;
        if (i < NC) {
            sc[i] = run;
            run += local[k];
        }
    }
    __syncthreads();
    for (int i = t; i < NC; i += 1024) {
        g_offsets[i] = sc[i];
        g_count[i] = 0;   // ready for next replay's hist
    }
    if (t == 1023) g_offsets[NC] = run;
}

// ---------------------------------------------------------------------------
// Atomic-free scatter: position = offsets[center] + rank (rank from hist).
// ---------------------------------------------------------------------------
__global__ void scatter_kernel() {
    int p = blockIdx.x * blockDim.x + threadIdx.x;
    if (p < NP) {
        unsigned e = g_packed[p];
        int c = e >> 18;
        int pos = g_offsets[c] + (int)(e & 0xFFFFu);
        g_order[pos] = ((unsigned)p << 2) | ((e >> 16) & 3u);
    }
}

// ---------------------------------------------------------------------------
// Packed FMA: acc(f32x2) += w(f32x2, replicated scalar) * v(f32x2). PTX-only
// (ptxas never auto-fuses FFMA2 from C++). Unpredicated.
// ---------------------------------------------------------------------------
#define FMA2(acc, w, v) \
    asm("fma.rn.f32x2 %0, %1, %2, %0;" : "+l"(acc) : "l"(w), "l"(v))

// one pair: v = (v01,v23), species sv; w column fetched from smem (2x LDS.128)
#define ACCP(sv, v)                                                          \
    do {                                                                     \
        ulonglong2 wa = swpk[(sv) * 2 + 0];                                  \
        ulonglong2 wb = swpk[(sv) * 2 + 1];                                  \
        FMA2(a01[0], wa.x, (v).x); FMA2(a23[0], wa.x, (v).y);                \
        FMA2(a01[1], wa.y, (v).x); FMA2(a23[1], wa.y, (v).y);                \
        FMA2(a01[2], wb.x, (v).x); FMA2(a23[2], wb.x, (v).y);                \
        FMA2(a01[3], wb.y, (v).x); FMA2(a23[3], wb.y, (v).y);                \
    } while (0)

// ---------------------------------------------------------------------------
// Main kernel: one CTA per center, 320 threads = 4 groups of 80. Each group's
// 80 16-byte slots cover the 320-float pair row (l0: 0-4, l1: 5-19,
// l2: 20-44, l3: 45-79). Groups take even quarters of the center's pair
// range; 4 pairs in flight per thread. Accumulation goes DIRECTLY into the 4
// pseudo channels: a[d] += W[d][s_p] * v (unpredicated packed FFMA2; the
// per-pair species selects a packed W column from smem — group-uniform, so
// the LDS broadcasts). Epilogue: 4-group reduce + coalesced store (no
// W-combine needed; accumulators are already the outputs).
// ---------------------------------------------------------------------------
__global__ __launch_bounds__(MAINT, 4) void main_kernel(
    const float4* __restrict__ v0, const float4* __restrict__ v1,
    const float4* __restrict__ v2, const float4* __restrict__ v3,
    const float* __restrict__ W, float* __restrict__ out) {
    __shared__ float acc[16 * 320];       // [group*4+pseudo][320]
    __shared__ ulonglong2 swpk[8];        // [species][2]: packed (W[d][s],W[d][s])
    int tid = threadIdx.x;
    if (tid < 16) {
        int d = tid & 3, s = tid >> 2;
        float w = W[d * 4 + s];
        float2 p2 = make_float2(w, w);
        ((unsigned long long*)swpk)[s * 4 + d] =
            *(const unsigned long long*)&p2;
    }
    __syncthreads();

    int center = blockIdx.x;
    int start = g_offsets[center];
    int end = g_offsets[center + 1];

    int g = tid / 80;
    int slot = tid - g * 80;

    const float4* base;
    int rowf4, loc;
    if (slot < 5)       { base = v0; rowf4 = 5;  loc = slot; }
    else if (slot < 20) { base = v1; rowf4 = 15; loc = slot - 5; }
    else if (slot < 45) { base = v2; rowf4 = 25; loc = slot - 20; }
    else                { base = v3; rowf4 = 35; loc = slot - 45; }

    unsigned long long a01[4] = {0ull, 0ull, 0ull, 0ull};
    unsigned long long a23[4] = {0ull, 0ull, 0ull, 0ull};

    int len = end - start;
    int q = len >> 2, rem = len & 3;
    int b0 = start + g * q + min(g, rem);
    int b1 = b0 + q + (g < rem ? 1 : 0);

    int j = b0;
    for (; j + 3 < b1; j += 4) {
        unsigned e0 = g_order[j];
        unsigned e1 = g_order[j + 1];
        unsigned e2 = g_order[j + 2];
        unsigned e3 = g_order[j + 3];
        ulonglong2 va = __ldg((const ulonglong2*)(base + (size_t)(e0 >> 2) * rowf4 + loc));
        ulonglong2 vb = __ldg((const ulonglong2*)(base + (size_t)(e1 >> 2) * rowf4 + loc));
        ulonglong2 vc = __ldg((const ulonglong2*)(base + (size_t)(e2 >> 2) * rowf4 + loc));
        ulonglong2 vd = __ldg((const ulonglong2*)(base + (size_t)(e3 >> 2) * rowf4 + loc));
        ACCP(e0 & 3, va);
        ACCP(e1 & 3, vb);
        ACCP(e2 & 3, vc);
        ACCP(e3 & 3, vd);
    }
    for (; j < b1; j++) {
        unsigned e0 = g_order[j];
        ulonglong2 va = __ldg((const ulonglong2*)(base + (size_t)(e0 >> 2) * rowf4 + loc));
        ACCP(e0 & 3, va);
    }

    ulonglong2* accv = (ulonglong2*)acc;
#pragma unroll
    for (int d = 0; d < 4; d++)
        accv[(g * 4 + d) * 80 + slot] = make_ulonglong2(a01[d], a23[d]);
    __syncthreads();

    // 4-group reduce + coalesced store: 1280 outputs, 4 per thread.
    float* outc = out + (size_t)center * 1280;
    for (int o = tid; o < 1280; o += MAINT) {
        int l = (o >= 80) + (o >= 320) + (o >= 720);
        int off_out = (l == 0) ? 0 : (l == 1) ? 80 : (l == 2) ? 320 : 720;
        int off_in  = (l == 0) ? 0 : (l == 1) ? 20 : (l == 2) ? 80 : 180;
        int i = o - off_out;
        int n = i % 20;
        int d = (i / 20) & 3;
        int c = i / 80;
        int e = off_in + c * 20 + n;
        outc[o] = acc[d * 320 + e] + acc[(4 + d) * 320 + e] +
                  acc[(8 + d) * 320 + e] + acc[(12 + d) * 320 + e];
    }
}

extern "C" void kernel_launch(void* const* d_in, const int* in_sizes, int n_in,
                              void* d_out, int out_size) {
    const float4* v0 = (const float4*)d_in[0];
    const float4* v1 = (const float4*)d_in[1];
    const float4* v2 = (const float4*)d_in[2];
    const float4* v3 = (const float4*)d_in[3];
    const float* W = (const float*)d_in[4];
    const int* sp = (const int*)d_in[5];
    const int* dens = (const int*)d_in[6];
    float* out = (float*)d_out;

    hist_kernel<<<(NP + 255) / 256, 256>>>(dens, sp);
    scan_kernel<<<1, 1024>>>();
    scatter_kernel<<<(NP + 255) / 256, 256>>>();
    main_kernel<<<NC, MAINT>>>(v0, v1, v2, v3, W, out);
}

// round 14
// speedup vs baseline: 1.2261x; 1.2261x over previous
#include <cuda_runtime.h>

#define NP 300000
#define NC 10000
#define MAINT 320

// ---- scratch (device globals; zero-initialized at module load) ----
__device__ int g_count[NC];          // re-zeroed by scan_kernel after use
__device__ int g_offsets[NC + 1];
__device__ unsigned g_packed[NP];    // (center<<18)|(species<<16)|rank
__device__ unsigned g_order[NP];     // (pair_index<<2)|species

// ---------------------------------------------------------------------------
// Histogram with fused int64/int32 detection. Odd 32-bit words of int64 index
// data (values < 2^31) are all zero; for int32 species values 0..3 the odds
// of 256 sampled words all being zero are 4^-256. The atomicAdd return value
// is the pair's rank within its center, so the scatter pass needs no atomics.
// ---------------------------------------------------------------------------
__global__ void hist_kernel(const int* __restrict__ dens,
                            const int* __restrict__ sp) {
    __shared__ int s_any;
    if (threadIdx.x == 0) s_any = 0;
    __syncthreads();
    if (threadIdx.x < 256) {
        int v = sp[2 * threadIdx.x + 1];
        if (v) atomicOr(&s_any, 1);
    }
    __syncthreads();
    int st = s_any ? 1 : 2;   // any nonzero odd word -> int32 (stride 1)

    int p = blockIdx.x * blockDim.x + threadIdx.x;
    if (p < NP) {
        int c = dens[p * st];
        int s = sp[p * st] & 3;
        unsigned rank = (unsigned)atomicAdd(&g_count[c], 1);
        g_packed[p] = ((unsigned)c << 18) | ((unsigned)s << 16) | rank;
    }
}

// ---------------------------------------------------------------------------
// Single-block exclusive scan over 10k counts; re-zeros g_count for the next
// graph replay (device globals are only auto-zeroed at module load).
// ---------------------------------------------------------------------------
__global__ __launch_bounds__(1024) void scan_kernel() {
    __shared__ int sc[NC];
    __shared__ int wsum[32];
    int t = threadIdx.x;
    for (int i = t; i < NC; i += 1024) sc[i] = g_count[i];
    __syncthreads();

    const int PER = (NC + 1023) / 1024;  // 10
    int base = t * PER;
    int local[PER];
    int sum = 0;
#pragma unroll
    for (int k = 0; k < PER; k++) {
        int i = base + k;
        int c = (i < NC) ? sc[i] : 0;
        local[k] = c;
        sum += c;
    }
    int lane = t & 31, warp = t >> 5;
    int inc = sum;
#pragma unroll
    for (int off = 1; off < 32; off <<= 1) {
        int n = __shfl_up_sync(0xffffffffu, inc, off);
        if (lane >= off) inc += n;
    }
    if (lane == 31) wsum[warp] = inc;
    __syncthreads();
    if (warp == 0) {
        int v = wsum[lane];
#pragma unroll
        for (int off = 1; off < 32; off <<= 1) {
            int n = __shfl_up_sync(0xffffffffu, v, off);
            if (lane >= off) v += n;
        }
        wsum[lane] = v;
    }
    __syncthreads();
    int run = inc - sum + (warp ? wsum[warp - 1] : 0);
#pragma unroll
    for (int k = 0; k < PER; k++) {
        int i = base + k;
        if (i < NC) {
            sc[i] = run;
            run += local[k];
        }
    }
    __syncthreads();
    for (int i = t; i < NC; i += 1024) {
        g_offsets[i] = sc[i];
        g_count[i] = 0;   // ready for next replay's hist
    }
    if (t == 1023) g_offsets[NC] = run;
}

// ---------------------------------------------------------------------------
// Atomic-free scatter: position = offsets[center] + rank (rank from hist).
// ---------------------------------------------------------------------------
__global__ void scatter_kernel() {
    int p = blockIdx.x * blockDim.x + threadIdx.x;
    if (p < NP) {
        unsigned e = g_packed[p];
        int c = e >> 18;
        int pos = g_offsets[c] + (int)(e & 0xFFFFu);
        g_order[pos] = ((unsigned)p << 2) | ((e >> 16) & 3u);
    }
}

// ---------------------------------------------------------------------------
// Main kernel (R10 structure + clamped full-MLP batches): one CTA per center,
// 320 threads = 4 groups of 80. Each group's 80 float4 slots cover the
// 320-float pair row (l0: 0-4, l1: 5-19, l2: 20-44, l3: 45-79). Groups take
// even quarters of the center's pair range. EVERY batch processes 4 pairs in
// flight: out-of-range lanes clamp their index to the last valid entry (an
// in-bounds duplicate load) and force species=4, which matches no accumulator
// -> contributes nothing. This removes the serial MLP=1 remainder loop that
// previously handled ~25% of all pairs. Per-species register accumulation
// (predicated adds), then 4-group reduce + W-combine + coalesced store.
// ---------------------------------------------------------------------------
__global__ __launch_bounds__(MAINT, 4) void main_kernel(
    const float4* __restrict__ v0, const float4* __restrict__ v1,
    const float4* __restrict__ v2, const float4* __restrict__ v3,
    const float* __restrict__ W, float* __restrict__ out) {
    __shared__ float acc[16 * 320];  // [group*4+species][320]
    __shared__ float sW[16];
    int tid = threadIdx.x;
    if (tid < 16) sW[tid] = W[tid];
    int center = blockIdx.x;
    int start = g_offsets[center];
    int end = g_offsets[center + 1];

    int g = tid / 80;
    int slot = tid - g * 80;

    const float4* base;
    int rowf4, loc;
    if (slot < 5)       { base = v0; rowf4 = 5;  loc = slot; }
    else if (slot < 20) { base = v1; rowf4 = 15; loc = slot - 5; }
    else if (slot < 45) { base = v2; rowf4 = 25; loc = slot - 20; }
    else                { base = v3; rowf4 = 35; loc = slot - 45; }

    float4 r[4];
#pragma unroll
    for (int s = 0; s < 4; s++) r[s] = make_float4(0.f, 0.f, 0.f, 0.f);

    int len = end - start;
    int q = len >> 2, rem = len & 3;
    int b0 = start + g * q + min(g, rem);
    int b1 = b0 + q + (g < rem ? 1 : 0);

    for (int j = b0; j < b1; j += 4) {
        int last = b1 - 1;
        int i1 = min(j + 1, last);
        int i2 = min(j + 2, last);
        int i3 = min(j + 3, last);
        unsigned e0 = g_order[j];
        unsigned e1 = g_order[i1];
        unsigned e2 = g_order[i2];
        unsigned e3 = g_order[i3];
        float4 va = __ldg(base + (size_t)(e0 >> 2) * rowf4 + loc);
        float4 vb = __ldg(base + (size_t)(e1 >> 2) * rowf4 + loc);
        float4 vc = __ldg(base + (size_t)(e2 >> 2) * rowf4 + loc);
        float4 vd = __ldg(base + (size_t)(e3 >> 2) * rowf4 + loc);
        int s0 = (int)(e0 & 3);
        int s1 = (j + 1 <= last) ? (int)(e1 & 3) : 4;  // 4 matches nothing
        int s2 = (j + 2 <= last) ? (int)(e2 & 3) : 4;
        int s3 = (j + 3 <= last) ? (int)(e3 & 3) : 4;
#pragma unroll
        for (int k = 0; k < 4; k++) {
            if (s0 == k) { r[k].x += va.x; r[k].y += va.y; r[k].z += va.z; r[k].w += va.w; }
        }
#pragma unroll
        for (int k = 0; k < 4; k++) {
            if (s1 == k) { r[k].x += vb.x; r[k].y += vb.y; r[k].z += vb.z; r[k].w += vb.w; }
        }
#pragma unroll
        for (int k = 0; k < 4; k++) {
            if (s2 == k) { r[k].x += vc.x; r[k].y += vc.y; r[k].z += vc.z; r[k].w += vc.w; }
        }
#pragma unroll
        for (int k = 0; k < 4; k++) {
            if (s3 == k) { r[k].x += vd.x; r[k].y += vd.y; r[k].z += vd.z; r[k].w += vd.w; }
        }
    }

    float4* accv = (float4*)acc;
#pragma unroll
    for (int s = 0; s < 4; s++)
        accv[(g * 4 + s) * 80 + slot] = r[s];
    __syncthreads();

    // W-combine + coalesced store: 1280 outputs, 4 per thread.
    float* outc = out + (size_t)center * 1280;
    for (int o = tid; o < 1280; o += MAINT) {
        int l = (o >= 80) + (o >= 320) + (o >= 720);
        int off_out = (l == 0) ? 0 : (l == 1) ? 80 : (l == 2) ? 320 : 720;
        int off_in  = (l == 0) ? 0 : (l == 1) ? 20 : (l == 2) ? 80 : 180;
        int i = o - off_out;
        int n = i % 20;
        int d = (i / 20) & 3;
        int c = i / 80;
        int e = off_in + c * 20 + n;
        float sum = 0.f;
#pragma unroll
        for (int s = 0; s < 4; s++) {
            float a = acc[s * 320 + e] + acc[(4 + s) * 320 + e] +
                      acc[(8 + s) * 320 + e] + acc[(12 + s) * 320 + e];
            sum = fmaf(sW[d * 4 + s], a, sum);
        }
        outc[o] = sum;
    }
}

extern "C" void kernel_launch(void* const* d_in, const int* in_sizes, int n_in,
                              void* d_out, int out_size) {
    const float4* v0 = (const float4*)d_in[0];
    const float4* v1 = (const float4*)d_in[1];
    const float4* v2 = (const float4*)d_in[2];
    const float4* v3 = (const float4*)d_in[3];
    const float* W = (const float*)d_in[4];
    const int* sp = (const int*)d_in[5];
    const int* dens = (const int*)d_in[6];
    float* out = (float*)d_out;

    hist_kernel<<<(NP + 255) / 256, 256>>>(dens, sp);
    scan_kernel<<<1, 1024>>>();
    scatter_kernel<<<(NP + 255) / 256, 256>>>();
    main_kernel<<<NC, MAINT>>>(v0, v1, v2, v3, W, out);
}